// round 16
// baseline (speedup 1.0000x reference)
#include <cuda_runtime.h>
#include <cuda_fp16.h>
#include <math.h>
#include <stdint.h>

#define NTOK 4096   // B*T
#define DDIM 1024
#define FDIM 4096
#define NEXP 8
#define NROWS (NTOK * 2)   // dispatch rows (top-2)

// GEMM tiling: 128x128 CTA tile, K-chunk 32, fp16 operands, 2-stage static smem
#define KCH 32
#define APITCH 80                    // 32 fp16 = 64B padded to 80B (odd 16B units)
#define BPITCH 272                   // 128 fp16 = 256B padded to 272B
#define A_TILE (128 * APITCH)        // 10240
#define B_TILE (KCH * BPITCH)        // 8704
#define STAGE  (A_TILE + B_TILE)     // 18944  (2 stages = 37888 < 48KB)

// ---------------- device scratch (~117MB) ----------------
__device__ int   g_count[NEXP];
__device__ int   g_cursor[NEXP];
__device__ int   g_offset[NEXP];
__device__ int   g_topk_idx[NTOK * 2];
__device__ float g_topk_w[NTOK * 2];
__device__ int   g_token_of_row[NROWS];
__device__ float g_w_of_row[NROWS];
__device__ int   g_row_of_token[NROWS];
__device__ __align__(16) __half g_Xh[(size_t)NROWS * DDIM];   // 16 MB
__device__ __align__(16) __half g_Hh[(size_t)NROWS * FDIM];   // 67 MB
__device__ __align__(16) float  g_Y[(size_t)NROWS * DDIM];    // 33.5 MB

// ---------------- helpers ----------------
__device__ __forceinline__ uint32_t smem_u32(const void* p) {
    uint32_t a;
    asm("{ .reg .u64 t; cvta.to.shared.u64 t, %1; cvt.u32.u64 %0, t; }" : "=r"(a) : "l"(p));
    return a;
}
__device__ __forceinline__ void ldm_x4(uint32_t (&r)[4], uint32_t a) {
    asm volatile("ldmatrix.sync.aligned.m8n8.x4.shared.b16 {%0,%1,%2,%3}, [%4];"
                 : "=r"(r[0]), "=r"(r[1]), "=r"(r[2]), "=r"(r[3]) : "r"(a));
}
__device__ __forceinline__ void ldm_x4t(uint32_t (&r)[4], uint32_t a) {
    asm volatile("ldmatrix.sync.aligned.m8n8.x4.trans.shared.b16 {%0,%1,%2,%3}, [%4];"
                 : "=r"(r[0]), "=r"(r[1]), "=r"(r[2]), "=r"(r[3]) : "r"(a));
}
__device__ __forceinline__ void mma16816f(float (&d)[4], const uint32_t (&a)[4],
                                          uint32_t b0, uint32_t b1) {
    asm volatile("mma.sync.aligned.m16n8k16.row.col.f32.f16.f16.f32 "
                 "{%0,%1,%2,%3}, {%4,%5,%6,%7}, {%8,%9}, {%0,%1,%2,%3};"
                 : "+f"(d[0]), "+f"(d[1]), "+f"(d[2]), "+f"(d[3])
                 : "r"(a[0]), "r"(a[1]), "r"(a[2]), "r"(a[3]), "r"(b0), "r"(b1));
}
__device__ __forceinline__ uint32_t f2h2(float a, float b) {
    __half2 h = __floats2half2_rn(a, b);
    return *reinterpret_cast<uint32_t*>(&h);
}
__device__ __forceinline__ float gelu_exact(float v) {
    return 0.5f * v * (1.0f + erff(v * 0.70710678118654752440f));
}

// ---------------- K0-K3: routing (unchanged, proven) ----------------
__global__ void zero_kernel() {
    int t = threadIdx.x;
    if (t < NEXP) { g_count[t] = 0; g_cursor[t] = 0; }
}

__global__ void router_kernel(const float* __restrict__ x,
                              const float* __restrict__ Wr) {
    int gwarp  = (blockIdx.x * blockDim.x + threadIdx.x) >> 5;
    int lane   = threadIdx.x & 31;
    int nwarps = (gridDim.x * blockDim.x) >> 5;
    for (int n = gwarp; n < NTOK; n += nwarps) {
        const float* xr = x + (size_t)n * DDIM;
        float acc[NEXP];
        #pragma unroll
        for (int e = 0; e < NEXP; e++) acc[e] = 0.f;
        for (int d = lane; d < DDIM; d += 32) {
            float xv = xr[d];
            const float* wr = Wr + (size_t)d * NEXP;
            float4 w0 = *(const float4*)(wr);
            float4 w1 = *(const float4*)(wr + 4);
            acc[0] = fmaf(xv, w0.x, acc[0]); acc[1] = fmaf(xv, w0.y, acc[1]);
            acc[2] = fmaf(xv, w0.z, acc[2]); acc[3] = fmaf(xv, w0.w, acc[3]);
            acc[4] = fmaf(xv, w1.x, acc[4]); acc[5] = fmaf(xv, w1.y, acc[5]);
            acc[6] = fmaf(xv, w1.z, acc[6]); acc[7] = fmaf(xv, w1.w, acc[7]);
        }
        #pragma unroll
        for (int e = 0; e < NEXP; e++)
            #pragma unroll
            for (int o = 16; o > 0; o >>= 1)
                acc[e] += __shfl_xor_sync(0xFFFFFFFFu, acc[e], o);
        if (lane == 0) {
            int i0 = 0; float v0 = acc[0];
            #pragma unroll
            for (int e = 1; e < NEXP; e++)
                if (acc[e] > v0) { v0 = acc[e]; i0 = e; }
            int i1 = -1; float v1 = -3.4e38f;
            #pragma unroll
            for (int e = 0; e < NEXP; e++)
                if (e != i0 && acc[e] > v1) { v1 = acc[e]; i1 = e; }
            float e1 = __expf(v1 - v0);
            float inv = 1.0f / (1.0f + e1);
            g_topk_idx[2 * n + 0] = i0;
            g_topk_idx[2 * n + 1] = i1;
            g_topk_w[2 * n + 0] = inv;
            g_topk_w[2 * n + 1] = e1 * inv;
            atomicAdd(&g_count[i0], 1);
            atomicAdd(&g_count[i1], 1);
        }
    }
}

__global__ void prefix_kernel() {
    int s = 0;
    for (int e = 0; e < NEXP; e++) { g_offset[e] = s; s += g_count[e]; }
}

__global__ void dispatch_kernel() {
    int n = blockIdx.x * blockDim.x + threadIdx.x;
    if (n >= NTOK) return;
    #pragma unroll
    for (int s = 0; s < 2; s++) {
        int e   = g_topk_idx[2 * n + s];
        int pos = atomicAdd(&g_cursor[e], 1);
        int row = g_offset[e] + pos;
        g_token_of_row[row] = n;
        g_w_of_row[row]     = g_topk_w[2 * n + s];
        g_row_of_token[2 * n + s] = row;
    }
}

// ---------------- K4: gather X -> fp16 ----------------
__global__ void gather_x_kernel(const float* __restrict__ x) {
    int r = blockIdx.x;
    int t = g_token_of_row[r];
    float4 v = ((const float4*)(x + (size_t)t * DDIM))[threadIdx.x];
    uint2 o = make_uint2(f2h2(v.x, v.y), f2h2(v.z, v.w));
    ((uint2*)(g_Xh + (size_t)r * DDIM))[threadIdx.x] = o;
}

// ---------------- GEMM: fp16 mma.sync m16n8k16, KCH=32 --------------------
// PH1: H(fp16) = gelu(Xh @ W1[e]);  grid (m, n, e)
// PH2: Y = w * (Hh @ W2[e]);        grid (n, m, e)
template<bool PH1>
__global__ __launch_bounds__(256, 2) void moe_gemm_kernel(const __half* __restrict__ Aglob,
                                                          const float* __restrict__ Wglob) {
    constexpr int K  = PH1 ? DDIM : FDIM;
    constexpr int NT = PH1 ? FDIM : DDIM;
    constexpr int NC = K / KCH;

    const int e   = blockIdx.z;
    const int cnt = g_count[e];
    const int m0  = (PH1 ? blockIdx.x : blockIdx.y) * 128;
    if (m0 >= cnt) return;
    const int n0  = (PH1 ? blockIdx.y : blockIdx.x) * 128;
    const int off = g_offset[e];
    const size_t rowbase = (size_t)off + m0;
    const float* Bsrc = Wglob + (size_t)e * K * NT + n0;

    __shared__ __align__(128) char smbuf[2][STAGE];
    __shared__ float wrow[128];

    const int tid  = threadIdx.x;
    const int warp = tid >> 5, lane = tid & 31;
    const int wm = warp & 1, wn = warp >> 1;    // 2x4 warps: 64m x 32n each

    if (!PH1 && tid < 128) {
        int r = m0 + tid;
        wrow[tid] = (r < cnt) ? g_w_of_row[off + r] : 0.f;
    }

    // loader roles:
    //   A: 128 rows x 64B; thread t: row = t>>1, half = t&1 (16 fp16 = 32B)
    //   B: 32 k-rows x 128 fp32; thread t: k = t>>3, seg = t&7 (16 fp32 -> 16 fp16)
    const int a_row = tid >> 1, a_half = tid & 1;
    const int b_k   = tid >> 3, b_seg = tid & 7;

    size_t ra = rowbase + a_row;
    if (ra >= NROWS) ra = 0;   // clamp (values discarded via epilogue bounds)
    const __half* aptr = Aglob + ra * (size_t)K;

    uint4  pa0, pa1;
    float4 pb[4];
    auto prefetch = [&](int kc) {
        pa0 = *(const uint4*)(aptr + kc + a_half * 16);
        pa1 = *(const uint4*)(aptr + kc + a_half * 16 + 8);
        const float* sb = Bsrc + (size_t)(kc + b_k) * NT + b_seg * 16;
        pb[0] = *(const float4*)(sb + 0);
        pb[1] = *(const float4*)(sb + 4);
        pb[2] = *(const float4*)(sb + 8);
        pb[3] = *(const float4*)(sb + 12);
    };
    auto store_stage = [&](int stg) {
        char* dst = smbuf[stg];
        *(uint4*)(dst + a_row * APITCH + a_half * 32)      = pa0;
        *(uint4*)(dst + a_row * APITCH + a_half * 32 + 16) = pa1;
        uint4 h0, h1;
        h0.x = f2h2(pb[0].x, pb[0].y); h0.y = f2h2(pb[0].z, pb[0].w);
        h0.z = f2h2(pb[1].x, pb[1].y); h0.w = f2h2(pb[1].z, pb[1].w);
        h1.x = f2h2(pb[2].x, pb[2].y); h1.y = f2h2(pb[2].z, pb[2].w);
        h1.z = f2h2(pb[3].x, pb[3].y); h1.w = f2h2(pb[3].z, pb[3].w);
        *(uint4*)(dst + A_TILE + b_k * BPITCH + b_seg * 32)      = h0;
        *(uint4*)(dst + A_TILE + b_k * BPITCH + b_seg * 32 + 16) = h1;
    };

    prefetch(0);
    store_stage(0);

    float acc[4][4][4];
    #pragma unroll
    for (int i = 0; i < 4; i++)
        #pragma unroll
        for (int j = 0; j < 4; j++)
            #pragma unroll
            for (int q = 0; q < 4; q++) acc[i][j][q] = 0.f;

    const uint32_t smb = smem_u32(smbuf);
    const int lrow = lane & 15;
    const int lk   = lane >> 4;
    const uint32_t aoff = (uint32_t)((wm * 64 + lrow) * APITCH + lk * 16);
    const uint32_t boff = (uint32_t)(A_TILE + lrow * BPITCH + wn * 64 + lk * 16);

    #pragma unroll 1
    for (int c = 0; c < NC; c++) {
        if (c + 1 < NC) prefetch((c + 1) * KCH);   // LDG issued before barrier
        __syncthreads();

        uint32_t stb = smb + (uint32_t)((c & 1) * STAGE);
        #pragma unroll
        for (int ks = 0; ks < 2; ks++) {           // two k16 sub-steps
            uint32_t bh[2][4];
            #pragma unroll
            for (int p = 0; p < 2; p++)
                ldm_x4t(bh[p], stb + boff + (uint32_t)(ks * 16 * BPITCH) + p * 32);
            #pragma unroll
            for (int mi = 0; mi < 4; mi++) {
                uint32_t ah[4];
                ldm_x4(ah, stb + aoff + (uint32_t)(mi * 16 * APITCH) + ks * 32);
                #pragma unroll
                for (int ni = 0; ni < 4; ni++) {
                    int p = ni >> 1, q = (ni & 1) * 2;
                    mma16816f(acc[mi][ni], ah, bh[p][q], bh[p][q + 1]);
                }
            }
        }
        if (c + 1 < NC) store_stage((c + 1) & 1);
    }

    // ---------------- epilogue ----------------
    const int ro  = lane >> 2;
    const int cp2 = (lane & 3) * 2;
    #pragma unroll
    for (int mi = 0; mi < 4; mi++)
        #pragma unroll
        for (int half = 0; half < 2; half++) {
            int lr = wm * 64 + mi * 16 + half * 8 + ro;
            if (m0 + lr < cnt) {
                size_t gr = rowbase + lr;
                if (PH1) {
                    __half* od = g_Hh + gr * (size_t)FDIM + n0 + wn * 32 + cp2;
                    #pragma unroll
                    for (int ni = 0; ni < 4; ni++) {
                        float f0 = gelu_exact(acc[mi][ni][half * 2 + 0]);
                        float f1 = gelu_exact(acc[mi][ni][half * 2 + 1]);
                        *(uint32_t*)(od + ni * 8) = f2h2(f0, f1);
                    }
                } else {
                    float w = wrow[lr];
                    float* od = g_Y + gr * (size_t)DDIM + n0 + wn * 32 + cp2;
                    #pragma unroll
                    for (int ni = 0; ni < 4; ni++) {
                        float2 v;
                        v.x = w * acc[mi][ni][half * 2 + 0];
                        v.y = w * acc[mi][ni][half * 2 + 1];
                        *(float2*)(od + ni * 8) = v;
                    }
                }
            }
        }
}

// ---------------- combine ----------------
__global__ void combine_kernel(float* __restrict__ out) {
    int idx = blockIdx.x * blockDim.x + threadIdx.x;
    if (idx >= NTOK * (DDIM / 4)) return;
    int n  = idx >> 8;
    int d4 = idx & 255;
    int r0 = g_row_of_token[2 * n + 0];
    int r1 = g_row_of_token[2 * n + 1];
    float4 a = *(const float4*)(g_Y + (size_t)r0 * DDIM + d4 * 4);
    float4 b = *(const float4*)(g_Y + (size_t)r1 * DDIM + d4 * 4);
    float4 o;
    o.x = a.x + b.x; o.y = a.y + b.y; o.z = a.z + b.z; o.w = a.w + b.w;
    ((float4*)out)[idx] = o;
}

// ---------------- launch ----------------
extern "C" void kernel_launch(void* const* d_in, const int* in_sizes, int n_in,
                              void* d_out, int out_size) {
    const float* x  = (const float*)d_in[0];
    const float* Wr = (const float*)d_in[1];
    const float* W1 = (const float*)d_in[2];   // [E][D][F]
    const float* W2 = (const float*)d_in[3];   // [E][F][D]
    float* out = (float*)d_out;

    zero_kernel<<<1, 32>>>();
    router_kernel<<<128, 256>>>(x, Wr);
    prefix_kernel<<<1, 1>>>();
    dispatch_kernel<<<(NTOK + 255) / 256, 256>>>();
    gather_x_kernel<<<NROWS, 256>>>(x);

    __half* xh = nullptr;
    __half* hh = nullptr;
    cudaGetSymbolAddress((void**)&xh, g_Xh);
    cudaGetSymbolAddress((void**)&hh, g_Hh);
    moe_gemm_kernel<true><<<dim3(NROWS / 128, FDIM / 128, NEXP), 256>>>(xh, W1);
    moe_gemm_kernel<false><<<dim3(DDIM / 128, NROWS / 128, NEXP), 256>>>(hh, W2);
    combine_kernel<<<(NTOK * (DDIM / 4) + 255) / 256, 256>>>(out);
}

// round 17
// speedup vs baseline: 1.0317x; 1.0317x over previous
#include <cuda_runtime.h>
#include <cuda_fp16.h>
#include <math.h>
#include <stdint.h>

#define NTOK 4096   // B*T
#define DDIM 1024
#define FDIM 4096
#define NEXP 8
#define NROWS (NTOK * 2)   // dispatch rows (top-2)

// GEMM tiling: 128x128 CTA tile, K-chunk 16, fp16 operands, 2-stage static smem
#define KCH 16
#define APITCH 48                    // 16 fp16 = 32B padded to 48B (odd 16B units)
#define BPITCH 272                   // 128 fp16 = 256B padded to 272B
#define A_TILE (128 * APITCH)        // 6144
#define B_TILE (KCH * BPITCH)        // 4352
#define STAGE  (A_TILE + B_TILE)     // 10496

// ---------------- device scratch (~251MB) ----------------
__device__ int   g_count[NEXP];
__device__ int   g_cursor[NEXP];
__device__ int   g_offset[NEXP];
__device__ int   g_topk_idx[NTOK * 2];
__device__ float g_topk_w[NTOK * 2];
__device__ int   g_token_of_row[NROWS];
__device__ float g_w_of_row[NROWS];
__device__ int   g_row_of_token[NROWS];
__device__ __align__(16) __half g_Xh[(size_t)NROWS * DDIM];          // 16 MB
__device__ __align__(16) __half g_Hh[(size_t)NROWS * FDIM];          // 67 MB
__device__ __align__(16) float  g_Y[(size_t)NROWS * DDIM];           // 33.5 MB
__device__ __align__(16) __half g_W1h[(size_t)NEXP * DDIM * FDIM];   // 67 MB
__device__ __align__(16) __half g_W2h[(size_t)NEXP * FDIM * DDIM];   // 67 MB

// ---------------- helpers ----------------
__device__ __forceinline__ uint32_t smem_u32(const void* p) {
    uint32_t a;
    asm("{ .reg .u64 t; cvta.to.shared.u64 t, %1; cvt.u32.u64 %0, t; }" : "=r"(a) : "l"(p));
    return a;
}
__device__ __forceinline__ void ldm_x4(uint32_t (&r)[4], uint32_t a) {
    asm volatile("ldmatrix.sync.aligned.m8n8.x4.shared.b16 {%0,%1,%2,%3}, [%4];"
                 : "=r"(r[0]), "=r"(r[1]), "=r"(r[2]), "=r"(r[3]) : "r"(a));
}
__device__ __forceinline__ void ldm_x4t(uint32_t (&r)[4], uint32_t a) {
    asm volatile("ldmatrix.sync.aligned.m8n8.x4.trans.shared.b16 {%0,%1,%2,%3}, [%4];"
                 : "=r"(r[0]), "=r"(r[1]), "=r"(r[2]), "=r"(r[3]) : "r"(a));
}
__device__ __forceinline__ void mma16816f(float (&d)[4], const uint32_t (&a)[4],
                                          uint32_t b0, uint32_t b1) {
    asm volatile("mma.sync.aligned.m16n8k16.row.col.f32.f16.f16.f32 "
                 "{%0,%1,%2,%3}, {%4,%5,%6,%7}, {%8,%9}, {%0,%1,%2,%3};"
                 : "+f"(d[0]), "+f"(d[1]), "+f"(d[2]), "+f"(d[3])
                 : "r"(a[0]), "r"(a[1]), "r"(a[2]), "r"(a[3]), "r"(b0), "r"(b1));
}
__device__ __forceinline__ uint32_t f2h2(float a, float b) {
    __half2 h = __floats2half2_rn(a, b);
    return *reinterpret_cast<uint32_t*>(&h);
}
__device__ __forceinline__ float gelu_exact(float v) {
    return 0.5f * v * (1.0f + erff(v * 0.70710678118654752440f));
}

// ---------------- K0-K3: routing (unchanged, proven) ----------------
__global__ void zero_kernel() {
    int t = threadIdx.x;
    if (t < NEXP) { g_count[t] = 0; g_cursor[t] = 0; }
}

__global__ void router_kernel(const float* __restrict__ x,
                              const float* __restrict__ Wr) {
    int gwarp  = (blockIdx.x * blockDim.x + threadIdx.x) >> 5;
    int lane   = threadIdx.x & 31;
    int nwarps = (gridDim.x * blockDim.x) >> 5;
    for (int n = gwarp; n < NTOK; n += nwarps) {
        const float* xr = x + (size_t)n * DDIM;
        float acc[NEXP];
        #pragma unroll
        for (int e = 0; e < NEXP; e++) acc[e] = 0.f;
        for (int d = lane; d < DDIM; d += 32) {
            float xv = xr[d];
            const float* wr = Wr + (size_t)d * NEXP;
            float4 w0 = *(const float4*)(wr);
            float4 w1 = *(const float4*)(wr + 4);
            acc[0] = fmaf(xv, w0.x, acc[0]); acc[1] = fmaf(xv, w0.y, acc[1]);
            acc[2] = fmaf(xv, w0.z, acc[2]); acc[3] = fmaf(xv, w0.w, acc[3]);
            acc[4] = fmaf(xv, w1.x, acc[4]); acc[5] = fmaf(xv, w1.y, acc[5]);
            acc[6] = fmaf(xv, w1.z, acc[6]); acc[7] = fmaf(xv, w1.w, acc[7]);
        }
        #pragma unroll
        for (int e = 0; e < NEXP; e++)
            #pragma unroll
            for (int o = 16; o > 0; o >>= 1)
                acc[e] += __shfl_xor_sync(0xFFFFFFFFu, acc[e], o);
        if (lane == 0) {
            int i0 = 0; float v0 = acc[0];
            #pragma unroll
            for (int e = 1; e < NEXP; e++)
                if (acc[e] > v0) { v0 = acc[e]; i0 = e; }
            int i1 = -1; float v1 = -3.4e38f;
            #pragma unroll
            for (int e = 0; e < NEXP; e++)
                if (e != i0 && acc[e] > v1) { v1 = acc[e]; i1 = e; }
            float e1 = __expf(v1 - v0);
            float inv = 1.0f / (1.0f + e1);
            g_topk_idx[2 * n + 0] = i0;
            g_topk_idx[2 * n + 1] = i1;
            g_topk_w[2 * n + 0] = inv;
            g_topk_w[2 * n + 1] = e1 * inv;
            atomicAdd(&g_count[i0], 1);
            atomicAdd(&g_count[i1], 1);
        }
    }
}

__global__ void prefix_kernel() {
    int s = 0;
    for (int e = 0; e < NEXP; e++) { g_offset[e] = s; s += g_count[e]; }
}

__global__ void dispatch_kernel() {
    int n = blockIdx.x * blockDim.x + threadIdx.x;
    if (n >= NTOK) return;
    #pragma unroll
    for (int s = 0; s < 2; s++) {
        int e   = g_topk_idx[2 * n + s];
        int pos = atomicAdd(&g_cursor[e], 1);
        int row = g_offset[e] + pos;
        g_token_of_row[row] = n;
        g_w_of_row[row]     = g_topk_w[2 * n + s];
        g_row_of_token[2 * n + s] = row;
    }
}

// ---------------- K4: gather X -> fp16 ----------------
__global__ void gather_x_kernel(const float* __restrict__ x) {
    int r = blockIdx.x;
    int t = g_token_of_row[r];
    float4 v = ((const float4*)(x + (size_t)t * DDIM))[threadIdx.x];
    uint2 o = make_uint2(f2h2(v.x, v.y), f2h2(v.z, v.w));
    ((uint2*)(g_Xh + (size_t)r * DDIM))[threadIdx.x] = o;
}

// ---------------- K5: convert weights fp32 -> fp16 (one pass) -------------
__global__ void convert_w_kernel(const float* __restrict__ in,
                                 __half* __restrict__ outh, int n4) {
    int i = blockIdx.x * blockDim.x + threadIdx.x;
    if (i >= n4) return;
    float4 v = ((const float4*)in)[i];
    ((uint2*)outh)[i] = make_uint2(f2h2(v.x, v.y), f2h2(v.z, v.w));
}

// ---------------- GEMM: fp16 mma.sync m16n8k16 (R15 engine, fp16 B) -------
// PH1: H(fp16) = gelu(Xh @ W1h[e]);  grid (m, n, e)
// PH2: Y = w * (Hh @ W2h[e]);        grid (n, m, e)
template<bool PH1>
__global__ __launch_bounds__(256, 2) void moe_gemm_kernel(const __half* __restrict__ Aglob,
                                                          const __half* __restrict__ Wglob) {
    constexpr int K  = PH1 ? DDIM : FDIM;
    constexpr int NT = PH1 ? FDIM : DDIM;
    constexpr int NC = K / KCH;

    const int e   = blockIdx.z;
    const int cnt = g_count[e];
    const int m0  = (PH1 ? blockIdx.x : blockIdx.y) * 128;
    if (m0 >= cnt) return;
    const int n0  = (PH1 ? blockIdx.y : blockIdx.x) * 128;
    const int off = g_offset[e];
    const size_t rowbase = (size_t)off + m0;
    const __half* Bsrc = Wglob + (size_t)e * K * NT + n0;

    __shared__ __align__(128) char smbuf[2][STAGE];
    __shared__ float wrow[128];

    const int tid  = threadIdx.x;
    const int warp = tid >> 5, lane = tid & 31;
    const int wm = warp & 1, wn = warp >> 1;    // 2x4 warps: 64m x 32n each

    if (!PH1 && tid < 128) {
        int r = m0 + tid;
        wrow[tid] = (r < cnt) ? g_w_of_row[off + r] : 0.f;
    }

    // loader roles: A 128 rows x 2 segs(8 fp16); B 16 k-rows x 16 segs(8 fp16)
    const int a_row = tid >> 1, a_seg = tid & 1;
    const int b_k   = tid >> 4, b_seg = tid & 15;

    size_t ra = rowbase + a_row;
    if (ra >= NROWS) ra = 0;   // clamp (values discarded via epilogue bounds)
    const __half* aptr = Aglob + ra * (size_t)K;

    uint4 pah, pbh;
    auto prefetch = [&](int kc) {
        pah = *(const uint4*)(aptr + kc + a_seg * 8);
        pbh = *(const uint4*)(Bsrc + (size_t)(kc + b_k) * NT + b_seg * 8);
    };
    auto store_stage = [&](int stg) {
        char* dst = smbuf[stg];
        *(uint4*)(dst + a_row * APITCH + a_seg * 16) = pah;
        *(uint4*)(dst + A_TILE + b_k * BPITCH + b_seg * 16) = pbh;
    };

    prefetch(0);
    store_stage(0);

    float acc[4][4][4];
    #pragma unroll
    for (int i = 0; i < 4; i++)
        #pragma unroll
        for (int j = 0; j < 4; j++)
            #pragma unroll
            for (int q = 0; q < 4; q++) acc[i][j][q] = 0.f;

    const uint32_t smb = smem_u32(smbuf);
    const int lrow = lane & 15;
    const int lk   = lane >> 4;
    const uint32_t aoff = (uint32_t)((wm * 64 + lrow) * APITCH + lk * 16);
    const uint32_t boff = (uint32_t)(A_TILE + lrow * BPITCH + wn * 64 + lk * 16);

    #pragma unroll 1
    for (int c = 0; c < NC; c++) {
        if (c + 1 < NC) prefetch((c + 1) * KCH);   // LDG issued before barrier
        __syncthreads();

        uint32_t stb = smb + (uint32_t)((c & 1) * STAGE);
        uint32_t bh[2][4];
        #pragma unroll
        for (int p = 0; p < 2; p++)
            ldm_x4t(bh[p], stb + boff + p * 32);
        #pragma unroll
        for (int mi = 0; mi < 4; mi++) {
            uint32_t ah[4];
            ldm_x4(ah, stb + aoff + mi * (16 * APITCH));
            #pragma unroll
            for (int ni = 0; ni < 4; ni++) {
                int p = ni >> 1, q = (ni & 1) * 2;
                mma16816f(acc[mi][ni], ah, bh[p][q], bh[p][q + 1]);
            }
        }
        if (c + 1 < NC) store_stage((c + 1) & 1);
    }

    // ---------------- epilogue ----------------
    const int ro  = lane >> 2;
    const int cp2 = (lane & 3) * 2;
    #pragma unroll
    for (int mi = 0; mi < 4; mi++)
        #pragma unroll
        for (int half = 0; half < 2; half++) {
            int lr = wm * 64 + mi * 16 + half * 8 + ro;
            if (m0 + lr < cnt) {
                size_t gr = rowbase + lr;
                if (PH1) {
                    __half* od = g_Hh + gr * (size_t)FDIM + n0 + wn * 32 + cp2;
                    #pragma unroll
                    for (int ni = 0; ni < 4; ni++) {
                        float f0 = gelu_exact(acc[mi][ni][half * 2 + 0]);
                        float f1 = gelu_exact(acc[mi][ni][half * 2 + 1]);
                        *(uint32_t*)(od + ni * 8) = f2h2(f0, f1);
                    }
                } else {
                    float w = wrow[lr];
                    float* od = g_Y + gr * (size_t)DDIM + n0 + wn * 32 + cp2;
                    #pragma unroll
                    for (int ni = 0; ni < 4; ni++) {
                        float2 v;
                        v.x = w * acc[mi][ni][half * 2 + 0];
                        v.y = w * acc[mi][ni][half * 2 + 1];
                        *(float2*)(od + ni * 8) = v;
                    }
                }
            }
        }
}

// ---------------- combine ----------------
__global__ void combine_kernel(float* __restrict__ out) {
    int idx = blockIdx.x * blockDim.x + threadIdx.x;
    if (idx >= NTOK * (DDIM / 4)) return;
    int n  = idx >> 8;
    int d4 = idx & 255;
    int r0 = g_row_of_token[2 * n + 0];
    int r1 = g_row_of_token[2 * n + 1];
    float4 a = *(const float4*)(g_Y + (size_t)r0 * DDIM + d4 * 4);
    float4 b = *(const float4*)(g_Y + (size_t)r1 * DDIM + d4 * 4);
    float4 o;
    o.x = a.x + b.x; o.y = a.y + b.y; o.z = a.z + b.z; o.w = a.w + b.w;
    ((float4*)out)[idx] = o;
}

// ---------------- launch ----------------
extern "C" void kernel_launch(void* const* d_in, const int* in_sizes, int n_in,
                              void* d_out, int out_size) {
    const float* x  = (const float*)d_in[0];
    const float* Wr = (const float*)d_in[1];
    const float* W1 = (const float*)d_in[2];   // [E][D][F]
    const float* W2 = (const float*)d_in[3];   // [E][F][D]
    float* out = (float*)d_out;

    zero_kernel<<<1, 32>>>();
    router_kernel<<<128, 256>>>(x, Wr);
    prefix_kernel<<<1, 1>>>();
    dispatch_kernel<<<(NTOK + 255) / 256, 256>>>();
    gather_x_kernel<<<NROWS, 256>>>(x);

    __half *w1h = nullptr, *w2h = nullptr, *xh = nullptr, *hh = nullptr;
    cudaGetSymbolAddress((void**)&w1h, g_W1h);
    cudaGetSymbolAddress((void**)&w2h, g_W2h);
    cudaGetSymbolAddress((void**)&xh, g_Xh);
    cudaGetSymbolAddress((void**)&hh, g_Hh);
    {
        int n4 = NEXP * DDIM * FDIM / 4;
        convert_w_kernel<<<(n4 + 255) / 256, 256>>>(W1, w1h, n4);
        convert_w_kernel<<<(n4 + 255) / 256, 256>>>(W2, w2h, n4);
    }
    moe_gemm_kernel<true><<<dim3(NROWS / 128, FDIM / 128, NEXP), 256>>>(xh, w1h);
    moe_gemm_kernel<false><<<dim3(DDIM / 128, NROWS / 128, NEXP), 256>>>(hh, w2h);
    combine_kernel<<<(NTOK * (DDIM / 4) + 255) / 256, 256>>>(out);
}